// round 5
// baseline (speedup 1.0000x reference)
#include <cuda_runtime.h>

// Per-quaternion L2 normalize: (65536, 1024) fp32 = 2^24 quats. Pure HBM
// stream, 512 MiB mandatory traffic.
// R1 MLP2 T256:  5955 GB/s (75.2%)
// R2 MLP4 T256:  6479 GB/s (81.8%)  kernel 74.3us
// R3 MLP8 T256:  6324 GB/s (79.8%)  regs 40 -> occ 62%, regression
// R4 MLP4 T512:  6451 GB/s (81.4%)  kernel 74.6us (== R2 plateau)
// R5: persistent one-wave grid (SMs*4 x 512thr, regs<=31 -> 64 warps/SM),
//     grid-stride loop unrolled x4. Removes ~13 wave transitions and keeps
//     the in-flight load pool saturated for the whole kernel.

static __device__ __forceinline__ float4 norm_quat(float4 v) {
    float s = v.x * v.x + v.y * v.y + v.z * v.z + v.w * v.w;
    float inv = (s == 0.0f) ? 1.0f : rsqrtf(s);
    v.x *= inv; v.y *= inv; v.z *= inv; v.w *= inv;
    return v;
}

__global__ void __launch_bounds__(512, 4)
quat_normalize_persistent(const float4* __restrict__ in,
                          float4* __restrict__ out,
                          int n_quat) {
    const int nthreads = gridDim.x * 512;          // total threads in grid
    int i = blockIdx.x * 512 + threadIdx.x;

    // Main loop: 4 independent, warp-coalesced 16B loads in flight per
    // thread per iteration (MLP_p1 = 4). Stores issue fire-and-forget,
    // then the next iteration's loads go out immediately.
    const int limit = n_quat - 3 * nthreads;
    for (; i < limit; i += 4 * nthreads) {
        float4 a = __ldcs(&in[i]);
        float4 b = __ldcs(&in[i + nthreads]);
        float4 c = __ldcs(&in[i + 2 * nthreads]);
        float4 d = __ldcs(&in[i + 3 * nthreads]);
        a = norm_quat(a);
        __stcs(&out[i], a);
        b = norm_quat(b);
        __stcs(&out[i + nthreads], b);
        c = norm_quat(c);
        __stcs(&out[i + 2 * nthreads], c);
        d = norm_quat(d);
        __stcs(&out[i + 3 * nthreads], d);
    }
    // Remainder (at most 3 elements per thread).
    for (; i < n_quat; i += nthreads)
        __stcs(&out[i], norm_quat(__ldcs(&in[i])));
}

extern "C" void kernel_launch(void* const* d_in, const int* in_sizes, int n_in,
                              void* d_out, int out_size) {
    const float4* x = (const float4*)d_in[0];
    float4* y = (float4*)d_out;
    int n_quat = in_sizes[0] / 4;   // 16,777,216

    int sms = 148;
    cudaDeviceGetAttribute(&sms, cudaDevAttrMultiProcessorCount, 0);

    // One full wave: 4 CTAs of 512 threads per SM (regs<=31, no smem).
    int blocks = sms * 4;
    quat_normalize_persistent<<<blocks, 512>>>(x, y, n_quat);
}

// round 6
// speedup vs baseline: 1.1210x; 1.1210x over previous
#include <cuda_runtime.h>

// Per-quaternion L2 normalize: (65536, 1024) fp32 = 2^24 quats. Pure HBM
// stream, 512 MiB mandatory traffic.
// R1 MLP2 T256:   5955 GB/s   wall 82.7
// R2 MLP4 T256:   6479 GB/s   wall 82.0   kernel 74.3us  <- plateau
// R3 MLP8 T256:   6324 GB/s   (regs 40 -> occ 62%)       regression
// R4 MLP4 T512:   6451 GB/s   wall 82.0   (== plateau)
// R5 persistent:  6077 GB/s   wall 92.2   loop deps serialize loads -> revert
// R6: Blackwell 256-bit ld/st (ld.global.v8.f32). Same 64B in flight per
//     thread as R2 but half the L1tex queue slots + half LSU issues.

struct f8 { float v[8]; };

static __device__ __forceinline__ f8 ldg256_cs(const float* p) {
    f8 r;
    asm volatile("ld.global.cs.v8.f32 {%0,%1,%2,%3,%4,%5,%6,%7}, [%8];"
                 : "=f"(r.v[0]), "=f"(r.v[1]), "=f"(r.v[2]), "=f"(r.v[3]),
                   "=f"(r.v[4]), "=f"(r.v[5]), "=f"(r.v[6]), "=f"(r.v[7])
                 : "l"(p));
    return r;
}

static __device__ __forceinline__ void stg256_cs(float* p, const f8& r) {
    asm volatile("st.global.cs.v8.f32 [%0], {%1,%2,%3,%4,%5,%6,%7,%8};"
                 :: "l"(p),
                    "f"(r.v[0]), "f"(r.v[1]), "f"(r.v[2]), "f"(r.v[3]),
                    "f"(r.v[4]), "f"(r.v[5]), "f"(r.v[6]), "f"(r.v[7])
                 : "memory");
}

// Normalize the two quaternions packed in an f8.
static __device__ __forceinline__ void norm2(f8& q) {
    float s0 = q.v[0]*q.v[0] + q.v[1]*q.v[1] + q.v[2]*q.v[2] + q.v[3]*q.v[3];
    float s1 = q.v[4]*q.v[4] + q.v[5]*q.v[5] + q.v[6]*q.v[6] + q.v[7]*q.v[7];
    float i0 = (s0 == 0.0f) ? 1.0f : rsqrtf(s0);
    float i1 = (s1 == 0.0f) ? 1.0f : rsqrtf(s1);
    q.v[0] *= i0; q.v[1] *= i0; q.v[2] *= i0; q.v[3] *= i0;
    q.v[4] *= i1; q.v[5] *= i1; q.v[6] *= i1; q.v[7] *= i1;
}

__global__ void __launch_bounds__(256)
quat_normalize_v8(const float* __restrict__ in, float* __restrict__ out) {
    const int T = 256;
    // Each thread: 2 x 256-bit loads (2 quats each) at warp-coalesced,
    // 32B-aligned addresses. Block covers 1024 quats = 16 KiB.
    long long q0 = (long long)blockIdx.x * (T * 4) + threadIdx.x * 2;   // quat idx
    long long q1 = q0 + T * 2;

    const float* p0 = in + q0 * 4;
    const float* p1 = in + q1 * 4;

    f8 a = ldg256_cs(p0);
    f8 b = ldg256_cs(p1);

    norm2(a);
    stg256_cs(out + q0 * 4, a);
    norm2(b);
    stg256_cs(out + q1 * 4, b);
}

// Bounds-checked fallback for non-multiple sizes (unused for 2^24 quats).
static __device__ __forceinline__ float4 norm_quat(float4 v) {
    float s = v.x * v.x + v.y * v.y + v.z * v.z + v.w * v.w;
    float inv = (s == 0.0f) ? 1.0f : rsqrtf(s);
    v.x *= inv; v.y *= inv; v.z *= inv; v.w *= inv;
    return v;
}

__global__ void __launch_bounds__(256)
quat_normalize_tail_kernel(const float4* __restrict__ in,
                           float4* __restrict__ out,
                           int n_quat) {
    int i = blockIdx.x * blockDim.x + threadIdx.x;
    if (i < n_quat) out[i] = norm_quat(__ldcs(&in[i]));
}

extern "C" void kernel_launch(void* const* d_in, const int* in_sizes, int n_in,
                              void* d_out, int out_size) {
    const float* x = (const float*)d_in[0];
    float* y = (float*)d_out;
    int n_quat = in_sizes[0] / 4;   // 16,777,216

    const int threads = 256;
    const int quats_per_block = threads * 4;  // 1024

    if (n_quat % quats_per_block == 0) {
        quat_normalize_v8<<<n_quat / quats_per_block, threads>>>(x, y);  // 16384 blocks
    } else {
        int main_blocks = n_quat / quats_per_block;
        if (main_blocks > 0)
            quat_normalize_v8<<<main_blocks, threads>>>(x, y);
        int done = main_blocks * quats_per_block;
        int rem = n_quat - done;
        if (rem > 0)
            quat_normalize_tail_kernel<<<(rem + 255) / 256, 256>>>(
                (const float4*)(x + (long long)done * 4),
                (float4*)(y + (long long)done * 4), rem);
    }
}